// round 2
// baseline (speedup 1.0000x reference)
#include <cuda_runtime.h>
#include <stdint.h>

// DAGNNConv: 10-hop normalized propagation + sigmoid-gated combination.
// N=100000 nodes, D=64 feats, E=1300000 edges (incl. self-loops), K=10 hops.
// src/dst delivered as int32 (JAX x64 disabled despite astype(int64)).

#define NNODES 100000
#define DIM    64
#define KHOPS  10
#define EMAX   1400000
#define SCAN_B 1024

__device__ int   g_deg[NNODES];
__device__ int   g_fill[NNODES];
__device__ float g_norm[NNODES];
__device__ int   g_rowoff[NNODES + 1];
__device__ int   g_part[256];
__device__ int2  g_edge[EMAX];                      // {src, __float_as_int(w)}
__device__ float g_H[(size_t)KHOPS * NNODES * DIM]; // hop results 1..10

// ---------------------------------------------------------------------------
__global__ void k_zero() {
    int i = blockIdx.x * blockDim.x + threadIdx.x;
    if (i < NNODES) { g_deg[i] = 0; g_fill[i] = 0; }
}

__global__ void k_count(const int* __restrict__ dst, int nE) {
    int e = blockIdx.x * blockDim.x + threadIdx.x;
    if (e >= nE) return;
    unsigned d = (unsigned)dst[e];
    if (d < NNODES) atomicAdd(&g_deg[d], 1);
}

// block-local exclusive scan of degrees; also compute norm = deg^-0.5
__global__ void k_scan1() {
    __shared__ int sh[SCAN_B];
    int idx = blockIdx.x * SCAN_B + threadIdx.x;
    int v = (idx < NNODES) ? g_deg[idx] : 0;
    if (idx < NNODES) g_norm[idx] = rsqrtf((float)v);
    sh[threadIdx.x] = v;
    __syncthreads();
    for (int off = 1; off < SCAN_B; off <<= 1) {
        int t = (threadIdx.x >= off) ? sh[threadIdx.x - off] : 0;
        __syncthreads();
        sh[threadIdx.x] += t;
        __syncthreads();
    }
    int incl = sh[threadIdx.x];
    if (idx < NNODES) g_rowoff[idx] = incl - v;   // block-local exclusive
    if (threadIdx.x == SCAN_B - 1) g_part[blockIdx.x] = incl;
}

// exclusive scan of block totals (tiny: <=128 values)
__global__ void k_scan2(int nb, int nE) {
    if (threadIdx.x == 0) {
        int run = 0;
        for (int b = 0; b < nb; b++) { int t = g_part[b]; g_part[b] = run; run += t; }
        g_rowoff[NNODES] = nE;
    }
}

__global__ void k_scan3() {
    int idx = blockIdx.x * SCAN_B + threadIdx.x;
    if (idx < NNODES) g_rowoff[idx] += g_part[blockIdx.x];
}

__global__ void k_scatter(const int* __restrict__ src,
                          const int* __restrict__ dst, int nE) {
    int e = blockIdx.x * blockDim.x + threadIdx.x;
    if (e >= nE) return;
    unsigned s = (unsigned)src[e];
    unsigned d = (unsigned)dst[e];
    if (s >= NNODES || d >= NNODES) return;
    int pos = g_rowoff[d] + atomicAdd(&g_fill[d], 1);
    if (pos < EMAX)
        g_edge[pos] = make_int2((int)s, __float_as_int(g_norm[s] * g_norm[d]));
}

// ---------------------------------------------------------------------------
// One propagation hop. Warp per destination node; lane owns channels
// {2*lane, 2*lane+1}. Per edge: broadcast edge record + coalesced 256B row
// gather from L2-resident prev matrix.
__global__ void __launch_bounds__(256)
k_spmm(const float* __restrict__ feats, int hop) {
    int v = blockIdx.x * 8 + (threadIdx.x >> 5);
    if (v >= NNODES) return;
    int lane = threadIdx.x & 31;

    const float* __restrict__ prev =
        (hop == 0) ? feats : (g_H + (size_t)(hop - 1) * NNODES * DIM);
    float* __restrict__ cur = g_H + (size_t)hop * NNODES * DIM;

    int beg = g_rowoff[v];
    int end = g_rowoff[v + 1];

    float a0 = 0.f, a1 = 0.f;
    int i = beg;
    // unroll by 2 for memory-level parallelism
    for (; i + 1 < end; i += 2) {
        int2 r0 = g_edge[i];
        int2 r1 = g_edge[i + 1];
        float2 h0 = *(const float2*)(prev + (size_t)r0.x * DIM + 2 * lane);
        float2 h1 = *(const float2*)(prev + (size_t)r1.x * DIM + 2 * lane);
        float w0 = __int_as_float(r0.y);
        float w1 = __int_as_float(r1.y);
        a0 = fmaf(w0, h0.x, a0); a1 = fmaf(w0, h0.y, a1);
        a0 = fmaf(w1, h1.x, a0); a1 = fmaf(w1, h1.y, a1);
    }
    if (i < end) {
        int2 r = g_edge[i];
        float2 h = *(const float2*)(prev + (size_t)r.x * DIM + 2 * lane);
        float w = __int_as_float(r.y);
        a0 = fmaf(w, h.x, a0); a1 = fmaf(w, h.y, a1);
    }
    float2 o; o.x = a0; o.y = a1;
    *(float2*)(cur + (size_t)v * DIM + 2 * lane) = o;
}

// ---------------------------------------------------------------------------
// Gate + combine. Warp per node; lane holds 2 channels of all 11 hop slices.
__global__ void __launch_bounds__(256)
k_gate(const float* __restrict__ feats, const float* __restrict__ s,
       float* __restrict__ out) {
    int v = blockIdx.x * 8 + (threadIdx.x >> 5);
    if (v >= NNODES) return;
    int lane = threadIdx.x & 31;

    float2 sv = *(const float2*)(s + 2 * lane);

    float2 h[KHOPS + 1];
    h[0] = *(const float2*)(feats + (size_t)v * DIM + 2 * lane);
#pragma unroll
    for (int k = 1; k <= KHOPS; k++)
        h[k] = *(const float2*)(g_H + (size_t)(k - 1) * NNODES * DIM +
                                (size_t)v * DIM + 2 * lane);

    float a0 = 0.f, a1 = 0.f;
#pragma unroll
    for (int k = 0; k <= KHOPS; k++) {
        float p = h[k].x * sv.x + h[k].y * sv.y;
#pragma unroll
        for (int o = 16; o; o >>= 1) p += __shfl_xor_sync(0xFFFFFFFFu, p, o);
        float g = 1.f / (1.f + __expf(-p));
        a0 = fmaf(g, h[k].x, a0);
        a1 = fmaf(g, h[k].y, a1);
    }
    float2 o2; o2.x = a0; o2.y = a1;
    *(float2*)(out + (size_t)v * DIM + 2 * lane) = o2;
}

// ---------------------------------------------------------------------------
extern "C" void kernel_launch(void* const* d_in, const int* in_sizes, int n_in,
                              void* d_out, int out_size) {
    const float* feats = (const float*)d_in[0];
    const float* s     = (const float*)d_in[1];
    const int*   src   = (const int*)d_in[2];
    const int*   dst   = (const int*)d_in[3];
    float*       out   = (float*)d_out;
    int nE = in_sizes[2];

    int nb = (NNODES + SCAN_B - 1) / SCAN_B;       // 98
    int eb = (nE + 255) / 256;
    int wb = (NNODES + 7) / 8;                     // 12500 (8 warps/block)

    k_zero<<<(NNODES + 255) / 256, 256>>>();
    k_count<<<eb, 256>>>(dst, nE);
    k_scan1<<<nb, SCAN_B>>>();
    k_scan2<<<1, 32>>>(nb, nE);
    k_scan3<<<nb, SCAN_B>>>();
    k_scatter<<<eb, 256>>>(src, dst, nE);

    for (int hop = 0; hop < KHOPS; hop++)
        k_spmm<<<wb, 256>>>(feats, hop);

    k_gate<<<wb, 256>>>(feats, s, out);
}

// round 3
// speedup vs baseline: 1.0167x; 1.0167x over previous
#include <cuda_runtime.h>
#include <cuda_fp16.h>
#include <stdint.h>

// DAGNNConv: 10-hop normalized propagation + sigmoid-gated combination.
// N=100000, D=64, E=1300000 (incl self-loops), K=10.
// Hop intermediates stored fp16 (half2) to halve L2 gather + DRAM traffic;
// all accumulation in fp32.

#define NNODES 100000
#define DIM    64
#define KHOPS  10
#define EMAX   1400000
#define SCAN_B 1024

__device__ int     g_deg[NNODES];
__device__ int     g_fill[NNODES];
__device__ float   g_norm[NNODES];
__device__ int     g_rowoff[NNODES + 1];
__device__ int     g_part[256];
__device__ int2    g_edge[EMAX];                        // {src, bits(w)}
__device__ __half2 g_H[(size_t)KHOPS * NNODES * 32];    // hop results, fp16

// ---------------------------------------------------------------------------
__global__ void k_zero() {
    int i = blockIdx.x * blockDim.x + threadIdx.x;
    if (i < NNODES) { g_deg[i] = 0; g_fill[i] = 0; }
}

__global__ void k_count(const int* __restrict__ dst, int nE) {
    int e = blockIdx.x * blockDim.x + threadIdx.x;
    if (e >= nE) return;
    unsigned d = (unsigned)dst[e];
    if (d < NNODES) atomicAdd(&g_deg[d], 1);
}

__global__ void k_scan1() {
    __shared__ int sh[SCAN_B];
    int idx = blockIdx.x * SCAN_B + threadIdx.x;
    int v = (idx < NNODES) ? g_deg[idx] : 0;
    if (idx < NNODES) g_norm[idx] = rsqrtf((float)v);
    sh[threadIdx.x] = v;
    __syncthreads();
    for (int off = 1; off < SCAN_B; off <<= 1) {
        int t = (threadIdx.x >= off) ? sh[threadIdx.x - off] : 0;
        __syncthreads();
        sh[threadIdx.x] += t;
        __syncthreads();
    }
    int incl = sh[threadIdx.x];
    if (idx < NNODES) g_rowoff[idx] = incl - v;
    if (threadIdx.x == SCAN_B - 1) g_part[blockIdx.x] = incl;
}

// parallel exclusive scan of <=128 block totals
__global__ void k_scan2(int nb, int nE) {
    __shared__ int sh[128];
    int v = (threadIdx.x < nb) ? g_part[threadIdx.x] : 0;
    sh[threadIdx.x] = v;
    __syncthreads();
    for (int off = 1; off < 128; off <<= 1) {
        int t = (threadIdx.x >= off) ? sh[threadIdx.x - off] : 0;
        __syncthreads();
        sh[threadIdx.x] += t;
        __syncthreads();
    }
    if (threadIdx.x < nb) g_part[threadIdx.x] = sh[threadIdx.x] - v;
    if (threadIdx.x == 0) g_rowoff[NNODES] = nE;
}

__global__ void k_scan3() {
    int idx = blockIdx.x * SCAN_B + threadIdx.x;
    if (idx < NNODES) g_rowoff[idx] += g_part[blockIdx.x];
}

__global__ void k_scatter(const int* __restrict__ src,
                          const int* __restrict__ dst, int nE) {
    int e = blockIdx.x * blockDim.x + threadIdx.x;
    if (e >= nE) return;
    unsigned s = (unsigned)src[e];
    unsigned d = (unsigned)dst[e];
    if (s >= NNODES || d >= NNODES) return;
    int pos = g_rowoff[d] + atomicAdd(&g_fill[d], 1);
    if (pos < EMAX)
        g_edge[pos] = make_int2((int)s, __float_as_int(g_norm[s] * g_norm[d]));
}

// ---------------------------------------------------------------------------
// Hop 0: gather fp32 feats rows, store fp16. Warp per node, lane owns
// channels {2*lane, 2*lane+1}.
__global__ void __launch_bounds__(256)
k_spmm0(const float* __restrict__ feats) {
    int v = blockIdx.x * 8 + (threadIdx.x >> 5);
    if (v >= NNODES) return;
    int lane = threadIdx.x & 31;

    int beg = g_rowoff[v], end = g_rowoff[v + 1];
    float a0 = 0.f, a1 = 0.f;
    for (int i = beg; i < end; i++) {
        int2 r = g_edge[i];
        float2 h = *(const float2*)(feats + (size_t)r.x * DIM + 2 * lane);
        float w = __int_as_float(r.y);
        a0 = fmaf(w, h.x, a0); a1 = fmaf(w, h.y, a1);
    }
    g_H[(size_t)v * 32 + lane] = __floats2half2_rn(a0, a1);
}

// Hops 1..9: gather fp16 rows (128 B/edge), accumulate fp32, store fp16.
__global__ void __launch_bounds__(256)
k_spmmh(int hop) {
    int v = blockIdx.x * 8 + (threadIdx.x >> 5);
    if (v >= NNODES) return;
    int lane = threadIdx.x & 31;

    const __half2* __restrict__ prev = g_H + (size_t)(hop - 1) * NNODES * 32;
    __half2* __restrict__ cur        = g_H + (size_t)hop * NNODES * 32;

    int beg = g_rowoff[v], end = g_rowoff[v + 1];
    float a0 = 0.f, a1 = 0.f;
    int i = beg;
    for (; i + 3 < end; i += 4) {
        int2 r0 = g_edge[i],     r1 = g_edge[i + 1];
        int2 r2 = g_edge[i + 2], r3 = g_edge[i + 3];
        float2 h0 = __half22float2(prev[(size_t)r0.x * 32 + lane]);
        float2 h1 = __half22float2(prev[(size_t)r1.x * 32 + lane]);
        float2 h2 = __half22float2(prev[(size_t)r2.x * 32 + lane]);
        float2 h3 = __half22float2(prev[(size_t)r3.x * 32 + lane]);
        float w0 = __int_as_float(r0.y), w1 = __int_as_float(r1.y);
        float w2 = __int_as_float(r2.y), w3 = __int_as_float(r3.y);
        a0 = fmaf(w0, h0.x, a0); a1 = fmaf(w0, h0.y, a1);
        a0 = fmaf(w1, h1.x, a0); a1 = fmaf(w1, h1.y, a1);
        a0 = fmaf(w2, h2.x, a0); a1 = fmaf(w2, h2.y, a1);
        a0 = fmaf(w3, h3.x, a0); a1 = fmaf(w3, h3.y, a1);
    }
    for (; i < end; i++) {
        int2 r = g_edge[i];
        float2 h = __half22float2(prev[(size_t)r.x * 32 + lane]);
        float w = __int_as_float(r.y);
        a0 = fmaf(w, h.x, a0); a1 = fmaf(w, h.y, a1);
    }
    cur[(size_t)v * 32 + lane] = __floats2half2_rn(a0, a1);
}

// ---------------------------------------------------------------------------
// Gate + combine. Warp per node; lane owns channels {2*lane, 2*lane+1}.
__global__ void __launch_bounds__(256)
k_gate(const float* __restrict__ feats, const float* __restrict__ s,
       float* __restrict__ out) {
    int v = blockIdx.x * 8 + (threadIdx.x >> 5);
    if (v >= NNODES) return;
    int lane = threadIdx.x & 31;

    float2 sv = *(const float2*)(s + 2 * lane);

    float2 h[KHOPS + 1];
    h[0] = *(const float2*)(feats + (size_t)v * DIM + 2 * lane);
#pragma unroll
    for (int k = 1; k <= KHOPS; k++)
        h[k] = __half22float2(
            g_H[(size_t)(k - 1) * NNODES * 32 + (size_t)v * 32 + lane]);

    float a0 = 0.f, a1 = 0.f;
#pragma unroll
    for (int k = 0; k <= KHOPS; k++) {
        float p = h[k].x * sv.x + h[k].y * sv.y;
#pragma unroll
        for (int o = 16; o; o >>= 1) p += __shfl_xor_sync(0xFFFFFFFFu, p, o);
        float g = 1.f / (1.f + __expf(-p));
        a0 = fmaf(g, h[k].x, a0);
        a1 = fmaf(g, h[k].y, a1);
    }
    float2 o2; o2.x = a0; o2.y = a1;
    *(float2*)(out + (size_t)v * DIM + 2 * lane) = o2;
}

// ---------------------------------------------------------------------------
extern "C" void kernel_launch(void* const* d_in, const int* in_sizes, int n_in,
                              void* d_out, int out_size) {
    const float* feats = (const float*)d_in[0];
    const float* s     = (const float*)d_in[1];
    const int*   src   = (const int*)d_in[2];
    const int*   dst   = (const int*)d_in[3];
    float*       out   = (float*)d_out;
    int nE = in_sizes[2];

    int nb = (NNODES + SCAN_B - 1) / SCAN_B;       // 98
    int eb = (nE + 255) / 256;
    int wb = (NNODES + 7) / 8;                     // 12500

    k_zero<<<(NNODES + 255) / 256, 256>>>();
    k_count<<<eb, 256>>>(dst, nE);
    k_scan1<<<nb, SCAN_B>>>();
    k_scan2<<<1, 128>>>(nb, nE);
    k_scan3<<<nb, SCAN_B>>>();
    k_scatter<<<eb, 256>>>(src, dst, nE);

    k_spmm0<<<wb, 256>>>(feats);
    for (int hop = 1; hop < KHOPS; hop++)
        k_spmmh<<<wb, 256>>>(hop);

    k_gate<<<wb, 256>>>(feats, s, out);
}

// round 5
// speedup vs baseline: 1.1160x; 1.0977x over previous
#include <cuda_runtime.h>
#include <cuda_fp16.h>
#include <stdint.h>

// DAGNNConv: 10-hop normalized propagation + sigmoid-gated combination.
// N=100000, D=64, E=1300000 (incl self-loops), K=10.
// Hop storage fp16. SpMM: 4 nodes/warp, 8 lanes/node, LDG.128 row gather,
// batched edge records via shfl. Device buffers selected INSIDE kernels
// (device symbols must not be passed from host).

#define NNODES 100000
#define DIM    64
#define KHOPS  10
#define EMAX   1400000
#define SCAN_B 1024

__device__ int     g_deg[NNODES];
__device__ int     g_fill[NNODES];
__device__ float   g_norm[NNODES];
__device__ int     g_rowoff[NNODES + 1];
__device__ int     g_part[256];
__device__ int2    g_edge[EMAX];                        // {src, bits(w)}
__device__ __half2 g_F16[(size_t)NNODES * 32];          // feats in fp16
__device__ __half2 g_H[(size_t)KHOPS * NNODES * 32];    // hop results, fp16

// ---------------------------------------------------------------------------
__global__ void k_zero() {
    int i = blockIdx.x * blockDim.x + threadIdx.x;
    if (i < NNODES) { g_deg[i] = 0; g_fill[i] = 0; }
}

__global__ void k_count(const int* __restrict__ dst, int nE) {
    int e = blockIdx.x * blockDim.x + threadIdx.x;
    if (e >= nE) return;
    unsigned d = (unsigned)dst[e];
    if (d < NNODES) atomicAdd(&g_deg[d], 1);
}

__global__ void k_scan1() {
    __shared__ int sh[SCAN_B];
    int idx = blockIdx.x * SCAN_B + threadIdx.x;
    int v = (idx < NNODES) ? g_deg[idx] : 0;
    if (idx < NNODES) g_norm[idx] = rsqrtf((float)v);
    sh[threadIdx.x] = v;
    __syncthreads();
    for (int off = 1; off < SCAN_B; off <<= 1) {
        int t = (threadIdx.x >= off) ? sh[threadIdx.x - off] : 0;
        __syncthreads();
        sh[threadIdx.x] += t;
        __syncthreads();
    }
    int incl = sh[threadIdx.x];
    if (idx < NNODES) g_rowoff[idx] = incl - v;
    if (threadIdx.x == SCAN_B - 1) g_part[blockIdx.x] = incl;
}

__global__ void k_scan2(int nb, int nE) {
    __shared__ int sh[128];
    int v = (threadIdx.x < nb) ? g_part[threadIdx.x] : 0;
    sh[threadIdx.x] = v;
    __syncthreads();
    for (int off = 1; off < 128; off <<= 1) {
        int t = (threadIdx.x >= off) ? sh[threadIdx.x - off] : 0;
        __syncthreads();
        sh[threadIdx.x] += t;
        __syncthreads();
    }
    if (threadIdx.x < nb) g_part[threadIdx.x] = sh[threadIdx.x] - v;
    if (threadIdx.x == 0) g_rowoff[NNODES] = nE;
}

__global__ void k_scan3() {
    int idx = blockIdx.x * SCAN_B + threadIdx.x;
    if (idx < NNODES) g_rowoff[idx] += g_part[blockIdx.x];
}

__global__ void k_scatter(const int* __restrict__ src,
                          const int* __restrict__ dst, int nE) {
    int e = blockIdx.x * blockDim.x + threadIdx.x;
    if (e >= nE) return;
    unsigned s = (unsigned)src[e];
    unsigned d = (unsigned)dst[e];
    if (s >= NNODES || d >= NNODES) return;
    int pos = g_rowoff[d] + atomicAdd(&g_fill[d], 1);
    if (pos < EMAX)
        g_edge[pos] = make_int2((int)s, __float_as_int(g_norm[s] * g_norm[d]));
}

// Convert feats fp32 -> fp16 row layout (32 half2 per node, channel order).
__global__ void k_cvt(const float* __restrict__ feats) {
    int i = blockIdx.x * blockDim.x + threadIdx.x;   // over NNODES*32
    if (i >= NNODES * 32) return;
    float2 f = *(const float2*)(feats + (size_t)i * 2);
    g_F16[i] = __floats2half2_rn(f.x, f.y);
}

// ---------------------------------------------------------------------------
// One hop. 4 nodes per warp; 8 lanes per node; lane owns 8 channels (16B).
// Per batch of 8 edges per group: 1 coalesced edge-record LDG + shfl
// distribution; per edge: one predicated LDG.128 serving 4 edges/warp.
__global__ void __launch_bounds__(256)
k_spmm(int hop) {
    int warp = blockIdx.x * 8 + (threadIdx.x >> 5);
    int lane = threadIdx.x & 31;
    int sub  = lane & 7;          // lane within group
    int gb   = lane & 24;         // first lane of my group
    int v    = warp * 4 + (lane >> 3);
    if (v >= NNODES) v = NNODES - 1;   // exact fit normally; safe clamp

    const uint4* __restrict__ prev = (const uint4*)(
        (hop == 0) ? g_F16 : (g_H + (size_t)(hop - 1) * NNODES * 32));
    uint4* __restrict__ cur = (uint4*)(g_H + (size_t)hop * NNODES * 32);

    int beg = g_rowoff[v];
    int deg = g_rowoff[v + 1] - beg;

    // warp-wide max degree (loop must stay converged for shfl)
    int maxdeg = deg;
#pragma unroll
    for (int o = 16; o; o >>= 1)
        maxdeg = max(maxdeg, __shfl_xor_sync(0xFFFFFFFFu, maxdeg, o));

    float a0 = 0.f, a1 = 0.f, a2 = 0.f, a3 = 0.f;
    float a4 = 0.f, a5 = 0.f, a6 = 0.f, a7 = 0.f;

    for (int base = 0; base < maxdeg; base += 8) {
        int idx = base + sub;
        int2 er = make_int2(0, 0);
        if (idx < deg) er = g_edge[beg + idx];

        int   srcs[8];
        float ws[8];
#pragma unroll
        for (int j = 0; j < 8; j++) {
            srcs[j] = __shfl_sync(0xFFFFFFFFu, er.x, gb + j);
            ws[j]   = __int_as_float(__shfl_sync(0xFFFFFFFFu, er.y, gb + j));
        }
#pragma unroll
        for (int j = 0; j < 8; j++) {
            if (base + j < deg) {
                uint4 raw = prev[(size_t)srcs[j] * 8 + sub];
                float2 f0 = __half22float2(*(const __half2*)&raw.x);
                float2 f1 = __half22float2(*(const __half2*)&raw.y);
                float2 f2 = __half22float2(*(const __half2*)&raw.z);
                float2 f3 = __half22float2(*(const __half2*)&raw.w);
                float w = ws[j];
                a0 = fmaf(w, f0.x, a0); a1 = fmaf(w, f0.y, a1);
                a2 = fmaf(w, f1.x, a2); a3 = fmaf(w, f1.y, a3);
                a4 = fmaf(w, f2.x, a4); a5 = fmaf(w, f2.y, a5);
                a6 = fmaf(w, f3.x, a6); a7 = fmaf(w, f3.y, a7);
            }
        }
    }

    uint4 o;
    *(__half2*)&o.x = __floats2half2_rn(a0, a1);
    *(__half2*)&o.y = __floats2half2_rn(a2, a3);
    *(__half2*)&o.z = __floats2half2_rn(a4, a5);
    *(__half2*)&o.w = __floats2half2_rn(a6, a7);
    cur[(size_t)v * 8 + sub] = o;
}

// ---------------------------------------------------------------------------
// Gate + combine. Warp per node; lane owns channels {2*lane, 2*lane+1}.
__global__ void __launch_bounds__(256)
k_gate(const float* __restrict__ feats, const float* __restrict__ s,
       float* __restrict__ out) {
    int v = blockIdx.x * 8 + (threadIdx.x >> 5);
    if (v >= NNODES) return;
    int lane = threadIdx.x & 31;

    float2 sv = *(const float2*)(s + 2 * lane);

    float2 h[KHOPS + 1];
    h[0] = *(const float2*)(feats + (size_t)v * DIM + 2 * lane);
#pragma unroll
    for (int k = 1; k <= KHOPS; k++)
        h[k] = __half22float2(
            g_H[(size_t)(k - 1) * NNODES * 32 + (size_t)v * 32 + lane]);

    float a0 = 0.f, a1 = 0.f;
#pragma unroll
    for (int k = 0; k <= KHOPS; k++) {
        float p = h[k].x * sv.x + h[k].y * sv.y;
#pragma unroll
        for (int o = 16; o; o >>= 1) p += __shfl_xor_sync(0xFFFFFFFFu, p, o);
        float g = 1.f / (1.f + __expf(-p));
        a0 = fmaf(g, h[k].x, a0);
        a1 = fmaf(g, h[k].y, a1);
    }
    float2 o2; o2.x = a0; o2.y = a1;
    *(float2*)(out + (size_t)v * DIM + 2 * lane) = o2;
}

// ---------------------------------------------------------------------------
extern "C" void kernel_launch(void* const* d_in, const int* in_sizes, int n_in,
                              void* d_out, int out_size) {
    const float* feats = (const float*)d_in[0];
    const float* s     = (const float*)d_in[1];
    const int*   src   = (const int*)d_in[2];
    const int*   dst   = (const int*)d_in[3];
    float*       out   = (float*)d_out;
    int nE = in_sizes[2];

    int nb = (NNODES + SCAN_B - 1) / SCAN_B;       // 98
    int eb = (nE + 255) / 256;
    int wb = (NNODES + 7) / 8;                     // 12500 (gate)
    int sb = (NNODES / 4 + 7) / 8;                 // 3125  (spmm: 4 nodes/warp)

    k_zero<<<(NNODES + 255) / 256, 256>>>();
    k_count<<<eb, 256>>>(dst, nE);
    k_scan1<<<nb, SCAN_B>>>();
    k_scan2<<<1, 128>>>(nb, nE);
    k_scan3<<<nb, SCAN_B>>>();
    k_scatter<<<eb, 256>>>(src, dst, nE);
    k_cvt<<<(NNODES * 32 + 255) / 256, 256>>>(feats);

    for (int hop = 0; hop < KHOPS; hop++)
        k_spmm<<<sb, 256>>>(hop);

    k_gate<<<wb, 256>>>(feats, s, out);
}